// round 10
// baseline (speedup 1.0000x reference)
#include <cuda_runtime.h>
#include <cuda_bf16.h>
#include <math_constants.h>
#include <cstdint>

#define NQ 32768
#define NM 2048
#define ND 512
#define BM 128
#define BN 128
#define BK 32
#define KTILES (ND / BK)
#define BKP 40
#define STAGE_ELEMS (128 * BKP)
#define STAGE_BYTES (STAGE_ELEMS * 2)
#define NSTAGE 3
#define SMEM_GEMM (2 * NSTAGE * STAGE_BYTES)   // 61440

#define CAND_CAP 512
#define NCAND 32
#define KTARGET 48           // histogram depth target: >=48 survivors

// __device__ globals = sanctioned scratch
__device__ float          g_S[(size_t)NQ * NM];
__device__ __nv_bfloat16  g_Ab[(size_t)NQ * ND];
__device__ __nv_bfloat16  g_Bb[(size_t)NM * ND];

__device__ __forceinline__ uint32_t smem_u32(const void* p) {
    uint32_t a;
    asm("{ .reg .u64 t; cvta.to.shared.u64 t, %1; cvt.u32.u64 %0, t; }"
        : "=r"(a) : "l"(p));
    return a;
}
#define CP16(dst, src) \
    asm volatile("cp.async.cg.shared.global [%0], [%1], 16;" \
                 :: "r"(dst), "l"(src) : "memory")
#define CP_COMMIT() asm volatile("cp.async.commit_group;" ::: "memory")
#define CP_WAIT1()  asm volatile("cp.async.wait_group 1;" ::: "memory")

#define LDMX4(r0, r1, r2, r3, addr) \
    asm volatile("ldmatrix.sync.aligned.m8n8.x4.shared.b16 {%0,%1,%2,%3}, [%4];" \
                 : "=r"(r0), "=r"(r1), "=r"(r2), "=r"(r3) : "r"(addr))

#define MMA16816(c, a, b0, b1) \
    asm volatile("mma.sync.aligned.m16n8k16.row.col.f32.bf16.bf16.f32 " \
                 "{%0,%1,%2,%3}, {%4,%5,%6,%7}, {%8,%9}, {%0,%1,%2,%3};" \
                 : "+f"((c)[0]), "+f"((c)[1]), "+f"((c)[2]), "+f"((c)[3]) \
                 : "r"((a)[0]), "r"((a)[1]), "r"((a)[2]), "r"((a)[3]),   \
                   "r"(b0), "r"(b1))

// FMA-pipe exp: 2^(x*log2e), degree-6 poly on frac, rel err ~1e-7, |x|<80.
__device__ __forceinline__ float pexp(float x) {
    float t = x * 1.4426950408889634f;
    float n = rintf(t);
    float f = t - n;
    float p = 1.5403530e-4f;
    p = fmaf(p, f, 1.3333558e-3f);
    p = fmaf(p, f, 9.6181291e-3f);
    p = fmaf(p, f, 5.5504109e-2f);
    p = fmaf(p, f, 2.4022651e-1f);
    p = fmaf(p, f, 6.9314718e-1f);
    p = fmaf(p, f, 1.0f);
    return __int_as_float(((int)n + 127) << 23) * p;
}

// ---------------------------------------------------------------------------
__global__ void tobf16_kernel(const float* __restrict__ X,
                              __nv_bfloat16* __restrict__ Y, int total) {
    int i = blockIdx.x * 256 + threadIdx.x;
    if (i < total) Y[i] = __float2bfloat16(X[i]);
}

// ---------------------------------------------------------------------------
// HMMA GEMM (known-good): g_S = Ab @ Bb^T
// ---------------------------------------------------------------------------
__device__ __forceinline__ void load_stage(uint32_t aBase, uint32_t bBase,
                                           int buf, int kt, int row0, int col0,
                                           int tid) {
#pragma unroll
    for (int i = 0; i < 2; i++) {
        int id = tid + (i << 8);
        int r  = id >> 2;
        int kc = (id & 3) << 3;
        uint32_t da = aBase + buf * STAGE_BYTES + (uint32_t)(r * BKP + kc) * 2;
        const __nv_bfloat16* ga = g_Ab + (size_t)(row0 + r) * ND + kt * BK + kc;
        CP16(da, ga);
        uint32_t db = bBase + buf * STAGE_BYTES + (uint32_t)(r * BKP + kc) * 2;
        const __nv_bfloat16* gb = g_Bb + (size_t)(col0 + r) * ND + kt * BK + kc;
        CP16(db, gb);
    }
}

__global__ __launch_bounds__(256)
void gemm_hmma() {
    extern __shared__ __nv_bfloat16 sm[];
    const int tid = threadIdx.x, lane = tid & 31, wid = tid >> 5;
    const int row0 = blockIdx.y * BM, col0 = blockIdx.x * BN;
    const int mw = (wid >> 1) * 32;
    const int nw = (wid & 1) * 64;
    uint32_t aBase = smem_u32(sm);
    uint32_t bBase = aBase + NSTAGE * STAGE_BYTES;

    const int a_row = lane & 15;
    const int a_k8  = (lane >> 4) << 3;
    const int b_row = (lane & 7) + ((lane >> 4) << 3);
    const int b_k8  = ((lane >> 3) & 1) << 3;

    float c[2][8][4];
#pragma unroll
    for (int mt = 0; mt < 2; mt++)
#pragma unroll
        for (int nt = 0; nt < 8; nt++)
#pragma unroll
            for (int r = 0; r < 4; r++) c[mt][nt][r] = 0.f;

    load_stage(aBase, bBase, 0, 0, row0, col0, tid); CP_COMMIT();
    load_stage(aBase, bBase, 1, 1, row0, col0, tid); CP_COMMIT();

    for (int s = 0; s < KTILES; s++) {
        if (s + 2 < KTILES)
            load_stage(aBase, bBase, (s + 2) % NSTAGE, s + 2, row0, col0, tid);
        CP_COMMIT();
        CP_WAIT1();
        __syncthreads();

        const int buf = s % NSTAGE;
#pragma unroll
        for (int k16 = 0; k16 < BK; k16 += 16) {
            uint32_t a[2][4], b[4][4];
#pragma unroll
            for (int mt = 0; mt < 2; mt++) {
                uint32_t addr = aBase + buf * STAGE_BYTES +
                    (uint32_t)((mw + mt * 16 + a_row) * BKP + k16 + a_k8) * 2;
                LDMX4(a[mt][0], a[mt][1], a[mt][2], a[mt][3], addr);
            }
#pragma unroll
            for (int np = 0; np < 4; np++) {
                uint32_t addr = bBase + buf * STAGE_BYTES +
                    (uint32_t)((nw + np * 16 + b_row) * BKP + k16 + b_k8) * 2;
                LDMX4(b[np][0], b[np][1], b[np][2], b[np][3], addr);
            }
#pragma unroll
            for (int mt = 0; mt < 2; mt++)
#pragma unroll
                for (int nt = 0; nt < 8; nt++)
                    MMA16816(c[mt][nt], a[mt],
                             b[nt >> 1][(nt & 1) * 2],
                             b[nt >> 1][(nt & 1) * 2 + 1]);
        }
        __syncthreads();
    }

#pragma unroll
    for (int mt = 0; mt < 2; mt++) {
        int r0r = row0 + mw + mt * 16 + (lane >> 2);
#pragma unroll
        for (int nt = 0; nt < 8; nt++) {
            int col = col0 + nw + nt * 8 + (lane & 3) * 2;
            float2 v0 = make_float2(c[mt][nt][0], c[mt][nt][1]);
            float2 v1 = make_float2(c[mt][nt][2], c[mt][nt][3]);
            *reinterpret_cast<float2*>(&g_S[(size_t)r0r * NM + col])       = v0;
            *reinterpret_cast<float2*>(&g_S[(size_t)(r0r + 8) * NM + col]) = v1;
        }
    }
}

// ---------------------------------------------------------------------------
// Rowpass v9: histogram-derived depth-48 threshold (no retry dynamics),
// single compaction, top-32 candidates, sequential-order exact fp32 rescore,
// exact top-10, Z term replacement, weights, gather+blend.
// ---------------------------------------------------------------------------
__global__ __launch_bounds__(256)
void rowpass_kernel(const float* __restrict__ Q, const float* __restrict__ Mi,
                    float* __restrict__ out) {
    __shared__ float4 ss4[NM / 4];        // 8 KB row cache
    __shared__ float  qs[ND];
    __shared__ float  sv[CAND_CAP];
    __shared__ int    si[CAND_CAP];
    __shared__ int    hist[32];
    __shared__ float  warpmax[8], warpsum[8];
    __shared__ float  cvC[NCAND];
    __shared__ int    ciC[NCAND];
    __shared__ float  ceC[NCAND];
    __shared__ float  selv[10];
    __shared__ int    seli[10];
    __shared__ float  zsh, mxsh, thrsh;
    __shared__ int    cnt, widef;

    const int tid = threadIdx.x, lane = tid & 31, wid = tid >> 5;
    const int row = blockIdx.x;
    const float4* srow4 = reinterpret_cast<const float4*>(g_S + (size_t)row * NM);

    if (tid < 10) { selv[tid] = 0.f; seli[tid] = 0; }
    if (tid < 32) hist[tid] = 0;
    if (tid == 0) cnt = 0;
    {
        const float2* q2 = reinterpret_cast<const float2*>(Q + (size_t)row * ND);
        reinterpret_cast<float2*>(qs)[tid] = q2[tid];
    }

    // pass 1: load row into smem cache, rowmax + Z (poly-exp)
    float lmax = -CUDART_INF_F, lsum = 0.f;
#pragma unroll
    for (int j = 0; j < 2; j++) {
        int idx = tid + (j << 8);
        float4 v = srow4[idx];
        ss4[idx] = v;
        lmax = fmaxf(fmaxf(lmax, fmaxf(v.x, v.y)), fmaxf(v.z, v.w));
        lsum += pexp(v.x) + pexp(v.y) + pexp(v.z) + pexp(v.w);
    }
#pragma unroll
    for (int o = 16; o; o >>= 1) {
        lmax = fmaxf(lmax, __shfl_xor_sync(~0u, lmax, o));
        lsum += __shfl_xor_sync(~0u, lsum, o);
    }
    if (lane == 0) { warpmax[wid] = lmax; warpsum[wid] = lsum; }
    __syncthreads();
    if (tid == 0) {
        float m = warpmax[0], z = warpsum[0];
        for (int w = 1; w < 8; w++) { m = fmaxf(m, warpmax[w]); z += warpsum[w]; }
        mxsh = m; zsh = z;
    }
    __syncthreads();
    const float mx = mxsh;

    // histogram (narrow): 32 bins of width 1/32 over (mx-1, mx]
#pragma unroll
    for (int j = 0; j < 2; j++) {
        float4 v = ss4[tid + (j << 8)];
#pragma unroll
        for (int c = 0; c < 4; c++) {
            float x = (c == 0) ? v.x : (c == 1) ? v.y : (c == 2) ? v.z : v.w;
            float d = (mx - x) * 32.f;
            if (d < 32.f) atomicAdd(&hist[(int)d], 1);
        }
    }
    __syncthreads();
    if (wid == 0) {
        int c = hist[lane];
#pragma unroll
        for (int o = 1; o < 32; o <<= 1) {
            int t = __shfl_up_sync(~0u, c, o);
            if (lane >= o) c += t;
        }
        unsigned m = __ballot_sync(~0u, c >= KTARGET);
        if (lane == 0) {
            if (m) {
                int b = __ffs(m) - 1;
                thrsh = mx - (float)(b + 1) * (1.f / 32.f);
                widef = 0;
            } else widef = 1;
        }
    }
    __syncthreads();

    if (widef) {   // rare (~3% of rows): outlier max, widen to (mx-4, mx]
        if (tid < 32) hist[tid] = 0;
        __syncthreads();
#pragma unroll
        for (int j = 0; j < 2; j++) {
            float4 v = ss4[tid + (j << 8)];
#pragma unroll
            for (int c = 0; c < 4; c++) {
                float x = (c == 0) ? v.x : (c == 1) ? v.y : (c == 2) ? v.z : v.w;
                float d = (mx - x) * 8.f;
                if (d < 32.f) atomicAdd(&hist[(int)d], 1);
            }
        }
        __syncthreads();
        if (wid == 0) {
            int c = hist[lane];
#pragma unroll
            for (int o = 1; o < 32; o <<= 1) {
                int t = __shfl_up_sync(~0u, c, o);
                if (lane >= o) c += t;
            }
            unsigned m = __ballot_sync(~0u, c >= KTARGET);
            if (lane == 0) {
                if (m) {
                    int b = __ffs(m) - 1;
                    thrsh = mx - (float)(b + 1) * 0.125f;
                } else thrsh = mx - 4.f;   // keep whatever is within 4.0
            }
        }
        __syncthreads();
    }
    const float thr = thrsh;

    // single compaction pass
#pragma unroll
    for (int j = 0; j < 2; j++) {
        int idx = tid + (j << 8);
        float4 v = ss4[idx];
        int base = idx << 2;
#pragma unroll
        for (int c = 0; c < 4; c++) {
            float x = (c == 0) ? v.x : (c == 1) ? v.y : (c == 2) ? v.z : v.w;
            if (x > thr) {
                int pos = atomicAdd(&cnt, 1);
                if (pos < CAND_CAP) { sv[pos] = x; si[pos] = base + c; }
            }
        }
    }
    __syncthreads();
    const int nsurv = (cnt < CAND_CAP) ? cnt : CAND_CAP;

    // warp 0: top-NCAND of survivors (value desc, index-asc tie-break)
    if (wid == 0) {
        for (int t = 0; t < NCAND; t++) {
            float lv = -CUDART_INF_F; int li = 0x7fffffff, lp = -1;
            for (int p = lane; p < nsurv; p += 32) {
                float v = sv[p]; int i = si[p];
                if (v > lv || (v == lv && i < li)) { lv = v; li = i; lp = p; }
            }
            float bv = lv; int bi = li;
#pragma unroll
            for (int o = 16; o; o >>= 1) {
                float ov = __shfl_xor_sync(~0u, bv, o);
                int   oi = __shfl_xor_sync(~0u, bi, o);
                if (ov > bv || (ov == bv && oi < bi)) { bv = ov; bi = oi; }
            }
            if (lane == 0) { cvC[t] = bv; ciC[t] = bi; }
            if (li == bi && lp >= 0) sv[lp] = -CUDART_INF_F;
            __syncwarp();
        }
    }
    __syncthreads();

    // EXACT rescore, reference-matching summation order: one thread per
    // candidate, single fp32 FMA chain over ascending k.
    if (tid < NCAND) {
        bool valid = cvC[tid] > -1e30f;
        int  mi = valid ? ciC[tid] : 0;
        const float4* m4 = reinterpret_cast<const float4*>(Mi + (size_t)mi * ND);
        const float4* q4 = reinterpret_cast<const float4*>(qs);
        float acc = 0.f;
#pragma unroll 8
        for (int it = 0; it < ND / 4; it++) {
            float4 a = q4[it], b = m4[it];
            acc = fmaf(a.x, b.x, acc);
            acc = fmaf(a.y, b.y, acc);
            acc = fmaf(a.z, b.z, acc);
            acc = fmaf(a.w, b.w, acc);
        }
        ceC[tid] = valid ? acc : -CUDART_INF_F;
    }
    __syncthreads();

    // warp 0: exact ranking of NCAND -> top-10; Z term replacement
    if (wid == 0) {
        float e  = ceC[lane];
        int   ii = ciC[lane];
        bool valid = (e > -1e30f);
        if (valid) {
            int rank = 0;
#pragma unroll
            for (int j = 0; j < NCAND; j++) {
                float ej = ceC[j]; int ij = ciC[j];
                rank += (ej > e) || (ej == e && ij < ii);
            }
            if (rank < 10) { selv[rank] = e; seli[rank] = ii; }
        }
        float dz = valid ? (pexp(e) - pexp(cvC[lane])) : 0.f;
#pragma unroll
        for (int o = 16; o; o >>= 1) dz += __shfl_xor_sync(~0u, dz, o);
        if (lane == 0) zsh += dz;
    }
    __syncthreads();

    const float Z = zsh;
    float p10[10];
#pragma unroll
    for (int j = 0; j < 10; j++) p10[j] = pexp(selv[j]) / Z;
    float wt[5], wb[5], st = 0.f, sb = 0.f;
#pragma unroll
    for (int j = 0; j < 5; j++) { wt[j] = pexp(p10[j]     - p10[0]); st += wt[j]; }
#pragma unroll
    for (int j = 0; j < 5; j++) { wb[j] = pexp(p10[5 + j] - p10[5]); sb += wb[j]; }
    const float rst = 1.f / st, rsb = 1.f / sb;
    int id[10];
#pragma unroll
    for (int j = 0; j < 10; j++) id[j] = seli[j];

    // gather + blend (float2 per thread; 512 = 256*2)
    {
        const int d = tid;
        float2 top = make_float2(0.f, 0.f), bot = make_float2(0.f, 0.f);
#pragma unroll
        for (int j = 0; j < 5; j++) {
            float2 m = reinterpret_cast<const float2*>(Mi + (size_t)id[j] * ND)[d];
            top.x += wt[j] * m.x; top.y += wt[j] * m.y;
        }
#pragma unroll
        for (int j = 0; j < 5; j++) {
            float2 m = reinterpret_cast<const float2*>(Mi + (size_t)id[5 + j] * ND)[d];
            bot.x += wb[j] * m.x; bot.y += wb[j] * m.y;
        }
        float2 q = reinterpret_cast<const float2*>(qs)[d];
        float2 o0, o1;
        o0.x = 0.5f  * q.x + 0.5f  * top.x * rst;
        o0.y = 0.5f  * q.y + 0.5f  * top.y * rst;
        o1.x = 0.01f * q.x + 0.99f * bot.x * rsb;
        o1.y = 0.01f * q.y + 0.99f * bot.y * rsb;
        reinterpret_cast<float2*>(out + (size_t)row * ND)[d] = o0;
        reinterpret_cast<float2*>(out + (size_t)NQ * ND + (size_t)row * ND)[d] = o1;
    }
}

// ---------------------------------------------------------------------------
extern "C" void kernel_launch(void* const* d_in, const int* in_sizes, int n_in,
                              void* d_out, int out_size) {
    const float* Q  = (const float*)d_in[0];
    const float* Mi = (const float*)d_in[1];
    if (n_in >= 2 && in_sizes[0] == NM * ND && in_sizes[1] == NQ * ND) {
        const float* t = Q; Q = Mi; Mi = t;
    }
    float* out = (float*)d_out;

    static int attr_done = 0;
    if (!attr_done) {
        cudaFuncSetAttribute(gemm_hmma,
                             cudaFuncAttributeMaxDynamicSharedMemorySize,
                             SMEM_GEMM);
        attr_done = 1;
    }

    __nv_bfloat16* gA;  cudaGetSymbolAddress((void**)&gA, g_Ab);
    __nv_bfloat16* gB;  cudaGetSymbolAddress((void**)&gB, g_Bb);
    tobf16_kernel<<<(NQ * ND + 255) / 256, 256>>>(Q,  gA, NQ * ND);
    tobf16_kernel<<<(NM * ND + 255) / 256, 256>>>(Mi, gB, NM * ND);

    dim3 gg(NM / BN, NQ / BM);
    gemm_hmma<<<gg, 256, SMEM_GEMM>>>();
    rowpass_kernel<<<NQ, 256>>>(Q, Mi, out);
}

// round 11
// speedup vs baseline: 1.0699x; 1.0699x over previous
#include <cuda_runtime.h>
#include <cuda_bf16.h>
#include <math_constants.h>
#include <cstdint>

#define NQ 32768
#define NM 2048
#define ND 512
#define BM 128
#define BN 128
#define BK 32
#define KTILES (ND / BK)
#define BKP 40
#define STAGE_ELEMS (128 * BKP)
#define STAGE_BYTES (STAGE_ELEMS * 2)
#define NSTAGE 3
#define SMEM_GEMM (2 * NSTAGE * STAGE_BYTES)   // 61440

#define CAND_CAP 512
#define NCAND 32
#define KTARGET 48

// __device__ globals = sanctioned scratch
__device__ float          g_S[(size_t)NQ * NM];
__device__ __nv_bfloat16  g_Ab[(size_t)NQ * ND];
__device__ __nv_bfloat16  g_Bb[(size_t)NM * ND];

__device__ __forceinline__ uint32_t smem_u32(const void* p) {
    uint32_t a;
    asm("{ .reg .u64 t; cvta.to.shared.u64 t, %1; cvt.u32.u64 %0, t; }"
        : "=r"(a) : "l"(p));
    return a;
}
#define CP16(dst, src) \
    asm volatile("cp.async.cg.shared.global [%0], [%1], 16;" \
                 :: "r"(dst), "l"(src) : "memory")
#define CP_COMMIT() asm volatile("cp.async.commit_group;" ::: "memory")
#define CP_WAIT1()  asm volatile("cp.async.wait_group 1;" ::: "memory")

#define LDMX4(r0, r1, r2, r3, addr) \
    asm volatile("ldmatrix.sync.aligned.m8n8.x4.shared.b16 {%0,%1,%2,%3}, [%4];" \
                 : "=r"(r0), "=r"(r1), "=r"(r2), "=r"(r3) : "r"(addr))

#define MMA16816(c, a, b0, b1) \
    asm volatile("mma.sync.aligned.m16n8k16.row.col.f32.bf16.bf16.f32 " \
                 "{%0,%1,%2,%3}, {%4,%5,%6,%7}, {%8,%9}, {%0,%1,%2,%3};" \
                 : "+f"((c)[0]), "+f"((c)[1]), "+f"((c)[2]), "+f"((c)[3]) \
                 : "r"((a)[0]), "r"((a)[1]), "r"((a)[2]), "r"((a)[3]),   \
                   "r"(b0), "r"(b1))

// FMA-pipe exp: 2^(x*log2e), degree-6 poly on frac, rel err ~1e-7, |x|<80.
__device__ __forceinline__ float pexp(float x) {
    float t = x * 1.4426950408889634f;
    float n = rintf(t);
    float f = t - n;
    float p = 1.5403530e-4f;
    p = fmaf(p, f, 1.3333558e-3f);
    p = fmaf(p, f, 9.6181291e-3f);
    p = fmaf(p, f, 5.5504109e-2f);
    p = fmaf(p, f, 2.4022651e-1f);
    p = fmaf(p, f, 6.9314718e-1f);
    p = fmaf(p, f, 1.0f);
    return __int_as_float(((int)n + 127) << 23) * p;
}

// ---------------------------------------------------------------------------
__global__ void tobf16_kernel(const float* __restrict__ X,
                              __nv_bfloat16* __restrict__ Y, int total) {
    int i = blockIdx.x * 256 + threadIdx.x;
    if (i < total) Y[i] = __float2bfloat16(X[i]);
}

// ---------------------------------------------------------------------------
// HMMA GEMM (known-good): g_S = Ab @ Bb^T
// ---------------------------------------------------------------------------
__device__ __forceinline__ void load_stage(uint32_t aBase, uint32_t bBase,
                                           int buf, int kt, int row0, int col0,
                                           int tid) {
#pragma unroll
    for (int i = 0; i < 2; i++) {
        int id = tid + (i << 8);
        int r  = id >> 2;
        int kc = (id & 3) << 3;
        uint32_t da = aBase + buf * STAGE_BYTES + (uint32_t)(r * BKP + kc) * 2;
        const __nv_bfloat16* ga = g_Ab + (size_t)(row0 + r) * ND + kt * BK + kc;
        CP16(da, ga);
        uint32_t db = bBase + buf * STAGE_BYTES + (uint32_t)(r * BKP + kc) * 2;
        const __nv_bfloat16* gb = g_Bb + (size_t)(col0 + r) * ND + kt * BK + kc;
        CP16(db, gb);
    }
}

__global__ __launch_bounds__(256)
void gemm_hmma() {
    extern __shared__ __nv_bfloat16 sm[];
    const int tid = threadIdx.x, lane = tid & 31, wid = tid >> 5;
    const int row0 = blockIdx.y * BM, col0 = blockIdx.x * BN;
    const int mw = (wid >> 1) * 32;
    const int nw = (wid & 1) * 64;
    uint32_t aBase = smem_u32(sm);
    uint32_t bBase = aBase + NSTAGE * STAGE_BYTES;

    const int a_row = lane & 15;
    const int a_k8  = (lane >> 4) << 3;
    const int b_row = (lane & 7) + ((lane >> 4) << 3);
    const int b_k8  = ((lane >> 3) & 1) << 3;

    float c[2][8][4];
#pragma unroll
    for (int mt = 0; mt < 2; mt++)
#pragma unroll
        for (int nt = 0; nt < 8; nt++)
#pragma unroll
            for (int r = 0; r < 4; r++) c[mt][nt][r] = 0.f;

    load_stage(aBase, bBase, 0, 0, row0, col0, tid); CP_COMMIT();
    load_stage(aBase, bBase, 1, 1, row0, col0, tid); CP_COMMIT();

    for (int s = 0; s < KTILES; s++) {
        if (s + 2 < KTILES)
            load_stage(aBase, bBase, (s + 2) % NSTAGE, s + 2, row0, col0, tid);
        CP_COMMIT();
        CP_WAIT1();
        __syncthreads();

        const int buf = s % NSTAGE;
#pragma unroll
        for (int k16 = 0; k16 < BK; k16 += 16) {
            uint32_t a[2][4], b[4][4];
#pragma unroll
            for (int mt = 0; mt < 2; mt++) {
                uint32_t addr = aBase + buf * STAGE_BYTES +
                    (uint32_t)((mw + mt * 16 + a_row) * BKP + k16 + a_k8) * 2;
                LDMX4(a[mt][0], a[mt][1], a[mt][2], a[mt][3], addr);
            }
#pragma unroll
            for (int np = 0; np < 4; np++) {
                uint32_t addr = bBase + buf * STAGE_BYTES +
                    (uint32_t)((nw + np * 16 + b_row) * BKP + k16 + b_k8) * 2;
                LDMX4(b[np][0], b[np][1], b[np][2], b[np][3], addr);
            }
#pragma unroll
            for (int mt = 0; mt < 2; mt++)
#pragma unroll
                for (int nt = 0; nt < 8; nt++)
                    MMA16816(c[mt][nt], a[mt],
                             b[nt >> 1][(nt & 1) * 2],
                             b[nt >> 1][(nt & 1) * 2 + 1]);
        }
        __syncthreads();
    }

#pragma unroll
    for (int mt = 0; mt < 2; mt++) {
        int r0r = row0 + mw + mt * 16 + (lane >> 2);
#pragma unroll
        for (int nt = 0; nt < 8; nt++) {
            int col = col0 + nw + nt * 8 + (lane & 3) * 2;
            float2 v0 = make_float2(c[mt][nt][0], c[mt][nt][1]);
            float2 v1 = make_float2(c[mt][nt][2], c[mt][nt][3]);
            *reinterpret_cast<float2*>(&g_S[(size_t)r0r * NM + col])       = v0;
            *reinterpret_cast<float2*>(&g_S[(size_t)(r0r + 8) * NM + col]) = v1;
        }
    }
}

// ---------------------------------------------------------------------------
// Rowpass v10: histogram depth-48 threshold; PARALLEL rank-based top-32;
// PARALLEL 8-way-split exact fp32 rescore (ascending-k segment chains,
// ordered combine); exact top-10; Z term replacement; weights; gather.
// ---------------------------------------------------------------------------
__global__ __launch_bounds__(256)
void rowpass_kernel(const float* __restrict__ Q, const float* __restrict__ Mi,
                    float* __restrict__ out) {
    __shared__ float4 ss4[NM / 4];        // 8 KB row cache
    __shared__ float  qs[ND];
    __shared__ float  sv[CAND_CAP];
    __shared__ int    si[CAND_CAP];
    __shared__ int    hist[32];
    __shared__ float  warpmax[8], warpsum[8];
    __shared__ float  cvC[NCAND];
    __shared__ int    ciC[NCAND];
    __shared__ float  ceC[NCAND];
    __shared__ float  part[NCAND][9];     // padded: conflict-free combine
    __shared__ float  selv[10];
    __shared__ int    seli[10];
    __shared__ float  zsh, mxsh, thrsh;
    __shared__ int    cnt, widef;

    const int tid = threadIdx.x, lane = tid & 31, wid = tid >> 5;
    const int row = blockIdx.x;
    const float4* srow4 = reinterpret_cast<const float4*>(g_S + (size_t)row * NM);

    if (tid < 10) { selv[tid] = 0.f; seli[tid] = 0; }
    if (tid < 32) { hist[tid] = 0; cvC[tid] = -CUDART_INF_F; ciC[tid] = 0; }
    if (tid == 0) cnt = 0;
    {
        const float2* q2 = reinterpret_cast<const float2*>(Q + (size_t)row * ND);
        reinterpret_cast<float2*>(qs)[tid] = q2[tid];
    }

    // pass 1: load row into smem cache, rowmax + Z (poly-exp)
    float lmax = -CUDART_INF_F, lsum = 0.f;
#pragma unroll
    for (int j = 0; j < 2; j++) {
        int idx = tid + (j << 8);
        float4 v = srow4[idx];
        ss4[idx] = v;
        lmax = fmaxf(fmaxf(lmax, fmaxf(v.x, v.y)), fmaxf(v.z, v.w));
        lsum += pexp(v.x) + pexp(v.y) + pexp(v.z) + pexp(v.w);
    }
#pragma unroll
    for (int o = 16; o; o >>= 1) {
        lmax = fmaxf(lmax, __shfl_xor_sync(~0u, lmax, o));
        lsum += __shfl_xor_sync(~0u, lsum, o);
    }
    if (lane == 0) { warpmax[wid] = lmax; warpsum[wid] = lsum; }
    __syncthreads();
    if (tid == 0) {
        float m = warpmax[0], z = warpsum[0];
        for (int w = 1; w < 8; w++) { m = fmaxf(m, warpmax[w]); z += warpsum[w]; }
        mxsh = m; zsh = z;
    }
    __syncthreads();
    const float mx = mxsh;

    // histogram: 32 bins of width 1/16 over (mx-2, mx]
#pragma unroll
    for (int j = 0; j < 2; j++) {
        float4 v = ss4[tid + (j << 8)];
#pragma unroll
        for (int c = 0; c < 4; c++) {
            float x = (c == 0) ? v.x : (c == 1) ? v.y : (c == 2) ? v.z : v.w;
            float d = (mx - x) * 16.f;
            if (d < 32.f) atomicAdd(&hist[(int)d], 1);
        }
    }
    __syncthreads();
    if (wid == 0) {
        int c = hist[lane];
#pragma unroll
        for (int o = 1; o < 32; o <<= 1) {
            int t = __shfl_up_sync(~0u, c, o);
            if (lane >= o) c += t;
        }
        unsigned m = __ballot_sync(~0u, c >= KTARGET);
        if (lane == 0) {
            if (m) {
                int b = __ffs(m) - 1;
                thrsh = mx - (float)(b + 1) * (1.f / 16.f);
                widef = 0;
            } else widef = 1;
        }
    }
    __syncthreads();

    if (widef) {   // rare: extreme outlier max, widen to (mx-4, mx]
        if (tid < 32) hist[tid] = 0;
        __syncthreads();
#pragma unroll
        for (int j = 0; j < 2; j++) {
            float4 v = ss4[tid + (j << 8)];
#pragma unroll
            for (int c = 0; c < 4; c++) {
                float x = (c == 0) ? v.x : (c == 1) ? v.y : (c == 2) ? v.z : v.w;
                float d = (mx - x) * 8.f;
                if (d < 32.f) atomicAdd(&hist[(int)d], 1);
            }
        }
        __syncthreads();
        if (wid == 0) {
            int c = hist[lane];
#pragma unroll
            for (int o = 1; o < 32; o <<= 1) {
                int t = __shfl_up_sync(~0u, c, o);
                if (lane >= o) c += t;
            }
            unsigned m = __ballot_sync(~0u, c >= KTARGET);
            if (lane == 0) {
                if (m) {
                    int b = __ffs(m) - 1;
                    thrsh = mx - (float)(b + 1) * 0.125f;
                } else thrsh = mx - 4.f;
            }
        }
        __syncthreads();
    }
    const float thr = thrsh;

    // single compaction pass
#pragma unroll
    for (int j = 0; j < 2; j++) {
        int idx = tid + (j << 8);
        float4 v = ss4[idx];
        int base = idx << 2;
#pragma unroll
        for (int c = 0; c < 4; c++) {
            float x = (c == 0) ? v.x : (c == 1) ? v.y : (c == 2) ? v.z : v.w;
            if (x > thr) {
                int pos = atomicAdd(&cnt, 1);
                if (pos < CAND_CAP) { sv[pos] = x; si[pos] = base + c; }
            }
        }
    }
    __syncthreads();
    const int nsurv = (cnt < CAND_CAP) ? cnt : CAND_CAP;

    // PARALLEL top-NCAND: rank each survivor by all-pairs comparison
    // (value desc, index asc — identical order to previous serial scan)
    for (int p = tid; p < nsurv; p += 256) {
        float v = sv[p]; int i = si[p];
        int rank = 0;
        for (int q = 0; q < nsurv; q++) {
            float vq = sv[q]; int iq = si[q];
            rank += (vq > v) || (vq == v && iq < i);
        }
        if (rank < NCAND) { cvC[rank] = v; ciC[rank] = i; }
    }
    __syncthreads();

    // PARALLEL exact rescore: candidate c = tid>>3, segment seg = tid&7.
    // Each segment is a sequential ascending-k fp32 FMA chain over 64 elems;
    // partials combined in ascending segment order (deterministic).
    {
        const int c = tid >> 3, seg = tid & 7;
        int mi_ = ciC[c];
        const float4* m4 = reinterpret_cast<const float4*>(Mi + (size_t)mi_ * ND)
                           + seg * 16;
        const float4* q4 = reinterpret_cast<const float4*>(qs) + seg * 16;
        float acc = 0.f;
#pragma unroll
        for (int it = 0; it < 16; it++) {
            float4 a = q4[it], b = m4[it];
            acc = fmaf(a.x, b.x, acc);
            acc = fmaf(a.y, b.y, acc);
            acc = fmaf(a.z, b.z, acc);
            acc = fmaf(a.w, b.w, acc);
        }
        part[c][seg] = acc;
    }
    __syncthreads();
    if (tid < NCAND) {
        float acc = part[tid][0];
#pragma unroll
        for (int s2 = 1; s2 < 8; s2++) acc += part[tid][s2];
        ceC[tid] = (cvC[tid] > -1e30f) ? acc : -CUDART_INF_F;
    }
    __syncthreads();

    // warp 0: exact ranking of NCAND -> top-10; Z term replacement
    if (wid == 0) {
        float e  = ceC[lane];
        int   ii = ciC[lane];
        bool valid = (e > -1e30f);
        if (valid) {
            int rank = 0;
#pragma unroll
            for (int j = 0; j < NCAND; j++) {
                float ej = ceC[j]; int ij = ciC[j];
                rank += (ej > e) || (ej == e && ij < ii);
            }
            if (rank < 10) { selv[rank] = e; seli[rank] = ii; }
        }
        float dz = valid ? (pexp(e) - pexp(cvC[lane])) : 0.f;
#pragma unroll
        for (int o = 16; o; o >>= 1) dz += __shfl_xor_sync(~0u, dz, o);
        if (lane == 0) zsh += dz;
    }
    __syncthreads();

    const float Z = zsh;
    float p10[10];
#pragma unroll
    for (int j = 0; j < 10; j++) p10[j] = pexp(selv[j]) / Z;
    float wt[5], wb[5], st = 0.f, sb = 0.f;
#pragma unroll
    for (int j = 0; j < 5; j++) { wt[j] = pexp(p10[j]     - p10[0]); st += wt[j]; }
#pragma unroll
    for (int j = 0; j < 5; j++) { wb[j] = pexp(p10[5 + j] - p10[5]); sb += wb[j]; }
    const float rst = 1.f / st, rsb = 1.f / sb;
    int id[10];
#pragma unroll
    for (int j = 0; j < 10; j++) id[j] = seli[j];

    // gather + blend (float2 per thread; 512 = 256*2)
    {
        const int d = tid;
        float2 top = make_float2(0.f, 0.f), bot = make_float2(0.f, 0.f);
#pragma unroll
        for (int j = 0; j < 5; j++) {
            float2 m = reinterpret_cast<const float2*>(Mi + (size_t)id[j] * ND)[d];
            top.x += wt[j] * m.x; top.y += wt[j] * m.y;
        }
#pragma unroll
        for (int j = 0; j < 5; j++) {
            float2 m = reinterpret_cast<const float2*>(Mi + (size_t)id[5 + j] * ND)[d];
            bot.x += wb[j] * m.x; bot.y += wb[j] * m.y;
        }
        float2 q = reinterpret_cast<const float2*>(qs)[d];
        float2 o0, o1;
        o0.x = 0.5f  * q.x + 0.5f  * top.x * rst;
        o0.y = 0.5f  * q.y + 0.5f  * top.y * rst;
        o1.x = 0.01f * q.x + 0.99f * bot.x * rsb;
        o1.y = 0.01f * q.y + 0.99f * bot.y * rsb;
        reinterpret_cast<float2*>(out + (size_t)row * ND)[d] = o0;
        reinterpret_cast<float2*>(out + (size_t)NQ * ND + (size_t)row * ND)[d] = o1;
    }
}

// ---------------------------------------------------------------------------
extern "C" void kernel_launch(void* const* d_in, const int* in_sizes, int n_in,
                              void* d_out, int out_size) {
    const float* Q  = (const float*)d_in[0];
    const float* Mi = (const float*)d_in[1];
    if (n_in >= 2 && in_sizes[0] == NM * ND && in_sizes[1] == NQ * ND) {
        const float* t = Q; Q = Mi; Mi = t;
    }
    float* out = (float*)d_out;

    static int attr_done = 0;
    if (!attr_done) {
        cudaFuncSetAttribute(gemm_hmma,
                             cudaFuncAttributeMaxDynamicSharedMemorySize,
                             SMEM_GEMM);
        attr_done = 1;
    }

    __nv_bfloat16* gA;  cudaGetSymbolAddress((void**)&gA, g_Ab);
    __nv_bfloat16* gB;  cudaGetSymbolAddress((void**)&gB, g_Bb);
    tobf16_kernel<<<(NQ * ND + 255) / 256, 256>>>(Q,  gA, NQ * ND);
    tobf16_kernel<<<(NM * ND + 255) / 256, 256>>>(Mi, gB, NM * ND);

    dim3 gg(NM / BN, NQ / BM);
    gemm_hmma<<<gg, 256, SMEM_GEMM>>>();
    rowpass_kernel<<<NQ, 256>>>(Q, Mi, out);
}

// round 12
// speedup vs baseline: 1.3009x; 1.2160x over previous
#include <cuda_runtime.h>
#include <cuda_bf16.h>
#include <math_constants.h>
#include <cstdint>

#define NQ 32768
#define NM 2048
#define ND 512
#define BM 128
#define BN 128
#define BK 32
#define KTILES (ND / BK)
#define BKP 40
#define STAGE_ELEMS (128 * BKP)
#define STAGE_BYTES (STAGE_ELEMS * 2)
#define NSTAGE 3
#define SMEM_GEMM (2 * NSTAGE * STAGE_BYTES)   // 61440

#define CAND_CAP 512
#define NCAND 32
#define KTARGET 48
#define RSTRIDE 516                       // candidate-row smem stride (floats)
#define SMEM_ROWS (NCAND * RSTRIDE * 4)   // 66048 bytes dynamic

// __device__ globals = sanctioned scratch
__device__ float          g_S[(size_t)NQ * NM];
__device__ __nv_bfloat16  g_Ab[(size_t)NQ * ND];
__device__ __nv_bfloat16  g_Bb[(size_t)NM * ND];

__device__ __forceinline__ uint32_t smem_u32(const void* p) {
    uint32_t a;
    asm("{ .reg .u64 t; cvta.to.shared.u64 t, %1; cvt.u32.u64 %0, t; }"
        : "=r"(a) : "l"(p));
    return a;
}
#define CP16(dst, src) \
    asm volatile("cp.async.cg.shared.global [%0], [%1], 16;" \
                 :: "r"(dst), "l"(src) : "memory")
#define CP_COMMIT() asm volatile("cp.async.commit_group;" ::: "memory")
#define CP_WAIT1()  asm volatile("cp.async.wait_group 1;" ::: "memory")

#define LDMX4(r0, r1, r2, r3, addr) \
    asm volatile("ldmatrix.sync.aligned.m8n8.x4.shared.b16 {%0,%1,%2,%3}, [%4];" \
                 : "=r"(r0), "=r"(r1), "=r"(r2), "=r"(r3) : "r"(addr))

#define MMA16816(c, a, b0, b1) \
    asm volatile("mma.sync.aligned.m16n8k16.row.col.f32.bf16.bf16.f32 " \
                 "{%0,%1,%2,%3}, {%4,%5,%6,%7}, {%8,%9}, {%0,%1,%2,%3};" \
                 : "+f"((c)[0]), "+f"((c)[1]), "+f"((c)[2]), "+f"((c)[3]) \
                 : "r"((a)[0]), "r"((a)[1]), "r"((a)[2]), "r"((a)[3]),   \
                   "r"(b0), "r"(b1))

// FMA-pipe exp: 2^(x*log2e), degree-6 poly on frac, rel err ~1e-7, |x|<80.
__device__ __forceinline__ float pexp(float x) {
    float t = x * 1.4426950408889634f;
    float n = rintf(t);
    float f = t - n;
    float p = 1.5403530e-4f;
    p = fmaf(p, f, 1.3333558e-3f);
    p = fmaf(p, f, 9.6181291e-3f);
    p = fmaf(p, f, 5.5504109e-2f);
    p = fmaf(p, f, 2.4022651e-1f);
    p = fmaf(p, f, 6.9314718e-1f);
    p = fmaf(p, f, 1.0f);
    return __int_as_float(((int)n + 127) << 23) * p;
}

// ---------------------------------------------------------------------------
__global__ void tobf16_kernel(const float* __restrict__ X,
                              __nv_bfloat16* __restrict__ Y, int total) {
    int i = blockIdx.x * 256 + threadIdx.x;
    if (i < total) Y[i] = __float2bfloat16(X[i]);
}

// ---------------------------------------------------------------------------
// HMMA GEMM (known-good): g_S = Ab @ Bb^T
// ---------------------------------------------------------------------------
__device__ __forceinline__ void load_stage(uint32_t aBase, uint32_t bBase,
                                           int buf, int kt, int row0, int col0,
                                           int tid) {
#pragma unroll
    for (int i = 0; i < 2; i++) {
        int id = tid + (i << 8);
        int r  = id >> 2;
        int kc = (id & 3) << 3;
        uint32_t da = aBase + buf * STAGE_BYTES + (uint32_t)(r * BKP + kc) * 2;
        const __nv_bfloat16* ga = g_Ab + (size_t)(row0 + r) * ND + kt * BK + kc;
        CP16(da, ga);
        uint32_t db = bBase + buf * STAGE_BYTES + (uint32_t)(r * BKP + kc) * 2;
        const __nv_bfloat16* gb = g_Bb + (size_t)(col0 + r) * ND + kt * BK + kc;
        CP16(db, gb);
    }
}

__global__ __launch_bounds__(256)
void gemm_hmma() {
    extern __shared__ __nv_bfloat16 sm[];
    const int tid = threadIdx.x, lane = tid & 31, wid = tid >> 5;
    const int row0 = blockIdx.y * BM, col0 = blockIdx.x * BN;
    const int mw = (wid >> 1) * 32;
    const int nw = (wid & 1) * 64;
    uint32_t aBase = smem_u32(sm);
    uint32_t bBase = aBase + NSTAGE * STAGE_BYTES;

    const int a_row = lane & 15;
    const int a_k8  = (lane >> 4) << 3;
    const int b_row = (lane & 7) + ((lane >> 4) << 3);
    const int b_k8  = ((lane >> 3) & 1) << 3;

    float c[2][8][4];
#pragma unroll
    for (int mt = 0; mt < 2; mt++)
#pragma unroll
        for (int nt = 0; nt < 8; nt++)
#pragma unroll
            for (int r = 0; r < 4; r++) c[mt][nt][r] = 0.f;

    load_stage(aBase, bBase, 0, 0, row0, col0, tid); CP_COMMIT();
    load_stage(aBase, bBase, 1, 1, row0, col0, tid); CP_COMMIT();

    for (int s = 0; s < KTILES; s++) {
        if (s + 2 < KTILES)
            load_stage(aBase, bBase, (s + 2) % NSTAGE, s + 2, row0, col0, tid);
        CP_COMMIT();
        CP_WAIT1();
        __syncthreads();

        const int buf = s % NSTAGE;
#pragma unroll
        for (int k16 = 0; k16 < BK; k16 += 16) {
            uint32_t a[2][4], b[4][4];
#pragma unroll
            for (int mt = 0; mt < 2; mt++) {
                uint32_t addr = aBase + buf * STAGE_BYTES +
                    (uint32_t)((mw + mt * 16 + a_row) * BKP + k16 + a_k8) * 2;
                LDMX4(a[mt][0], a[mt][1], a[mt][2], a[mt][3], addr);
            }
#pragma unroll
            for (int np = 0; np < 4; np++) {
                uint32_t addr = bBase + buf * STAGE_BYTES +
                    (uint32_t)((nw + np * 16 + b_row) * BKP + k16 + b_k8) * 2;
                LDMX4(b[np][0], b[np][1], b[np][2], b[np][3], addr);
            }
#pragma unroll
            for (int mt = 0; mt < 2; mt++)
#pragma unroll
                for (int nt = 0; nt < 8; nt++)
                    MMA16816(c[mt][nt], a[mt],
                             b[nt >> 1][(nt & 1) * 2],
                             b[nt >> 1][(nt & 1) * 2 + 1]);
        }
        __syncthreads();
    }

#pragma unroll
    for (int mt = 0; mt < 2; mt++) {
        int r0r = row0 + mw + mt * 16 + (lane >> 2);
#pragma unroll
        for (int nt = 0; nt < 8; nt++) {
            int col = col0 + nw + nt * 8 + (lane & 3) * 2;
            float2 v0 = make_float2(c[mt][nt][0], c[mt][nt][1]);
            float2 v1 = make_float2(c[mt][nt][2], c[mt][nt][3]);
            *reinterpret_cast<float2*>(&g_S[(size_t)r0r * NM + col])       = v0;
            *reinterpret_cast<float2*>(&g_S[(size_t)(r0r + 8) * NM + col]) = v1;
        }
    }
}

// ---------------------------------------------------------------------------
// Rowpass v11: scores kept in REGISTERS (no smem row cache); warp-aggregated
// histogram + compaction atomics; rank-based top-32; candidate rows staged
// into smem with COALESCED warp loads; SEQUENTIAL ascending-k fp32 rescore
// chains (bit-identical to round-10's reference-matching order) from smem.
// ---------------------------------------------------------------------------
__global__ __launch_bounds__(256)
void rowpass_kernel(const float* __restrict__ Q, const float* __restrict__ Mi,
                    float* __restrict__ out) {
    extern __shared__ float rowsm[];      // NCAND x RSTRIDE floats (66 KB)
    __shared__ float  qs[ND];
    __shared__ float  sv[CAND_CAP];
    __shared__ int    si[CAND_CAP];
    __shared__ int    hist[32];
    __shared__ float  warpmax[8], warpsum[8];
    __shared__ float  cvC[NCAND];
    __shared__ int    ciC[NCAND];
    __shared__ float  ceC[NCAND];
    __shared__ float  selv[10];
    __shared__ int    seli[10];
    __shared__ float  zsh, mxsh, thrsh;
    __shared__ int    cnt, widef;

    const int tid = threadIdx.x, lane = tid & 31, wid = tid >> 5;
    const int row = blockIdx.x;
    const float4* srow4 = reinterpret_cast<const float4*>(g_S + (size_t)row * NM);

    if (tid < 10) { selv[tid] = 0.f; seli[tid] = 0; }
    if (tid < 32) { hist[tid] = 0; cvC[tid] = -CUDART_INF_F; ciC[tid] = 0; }
    if (tid == 0) cnt = 0;
    {
        const float2* q2 = reinterpret_cast<const float2*>(Q + (size_t)row * ND);
        reinterpret_cast<float2*>(qs)[tid] = q2[tid];
    }

    // pass 1: load 8 scores into REGISTERS, rowmax + Z (poly-exp)
    float4 v0 = srow4[tid];
    float4 v1 = srow4[tid + 256];
    float e0[8] = {v0.x, v0.y, v0.z, v0.w, v1.x, v1.y, v1.z, v1.w};
    float lmax = -CUDART_INF_F, lsum = 0.f;
#pragma unroll
    for (int j = 0; j < 8; j++) {
        lmax = fmaxf(lmax, e0[j]);
        lsum += pexp(e0[j]);
    }
#pragma unroll
    for (int o = 16; o; o >>= 1) {
        lmax = fmaxf(lmax, __shfl_xor_sync(~0u, lmax, o));
        lsum += __shfl_xor_sync(~0u, lsum, o);
    }
    if (lane == 0) { warpmax[wid] = lmax; warpsum[wid] = lsum; }
    __syncthreads();
    if (tid == 0) {
        float m = warpmax[0], z = warpsum[0];
        for (int w = 1; w < 8; w++) { m = fmaxf(m, warpmax[w]); z += warpsum[w]; }
        mxsh = m; zsh = z;
    }
    __syncthreads();
    const float mx = mxsh;

    // histogram (32 bins, width 1/16 over (mx-2, mx]) — warp-aggregated atomics
#pragma unroll
    for (int j = 0; j < 8; j++) {
        float d = (mx - e0[j]) * 16.f;
        bool inr = d < 32.f;
        int bin = inr ? (int)d : 0;
        unsigned act = __ballot_sync(~0u, inr);
        if (inr) {
            unsigned m = __match_any_sync(act, bin);
            int leader = __ffs(m) - 1;
            if (lane == leader) atomicAdd(&hist[bin], __popc(m));
        }
    }
    __syncthreads();
    if (wid == 0) {
        int c = hist[lane];
#pragma unroll
        for (int o = 1; o < 32; o <<= 1) {
            int t = __shfl_up_sync(~0u, c, o);
            if (lane >= o) c += t;
        }
        unsigned m = __ballot_sync(~0u, c >= KTARGET);
        if (lane == 0) {
            if (m) {
                int b = __ffs(m) - 1;
                thrsh = mx - (float)(b + 1) * (1.f / 16.f);
                widef = 0;
            } else widef = 1;
        }
    }
    __syncthreads();

    if (widef) {   // rare: outlier max, widen to (mx-4, mx]
        if (tid < 32) hist[tid] = 0;
        __syncthreads();
#pragma unroll
        for (int j = 0; j < 8; j++) {
            float d = (mx - e0[j]) * 8.f;
            bool inr = d < 32.f;
            int bin = inr ? (int)d : 0;
            unsigned act = __ballot_sync(~0u, inr);
            if (inr) {
                unsigned m = __match_any_sync(act, bin);
                int leader = __ffs(m) - 1;
                if (lane == leader) atomicAdd(&hist[bin], __popc(m));
            }
        }
        __syncthreads();
        if (wid == 0) {
            int c = hist[lane];
#pragma unroll
            for (int o = 1; o < 32; o <<= 1) {
                int t = __shfl_up_sync(~0u, c, o);
                if (lane >= o) c += t;
            }
            unsigned m = __ballot_sync(~0u, c >= KTARGET);
            if (lane == 0) {
                if (m) {
                    int b = __ffs(m) - 1;
                    thrsh = mx - (float)(b + 1) * 0.125f;
                } else thrsh = mx - 4.f;
            }
        }
        __syncthreads();
    }
    const float thr = thrsh;

    // compaction from registers — warp-aggregated offsets
#pragma unroll
    for (int j = 0; j < 8; j++) {
        float x = e0[j];
        int idx = (j < 4) ? (tid * 4 + j) : ((tid + 256) * 4 + (j - 4));
        bool pred = x > thr;
        unsigned m = __ballot_sync(~0u, pred);
        int nw = __popc(m);
        int base = 0;
        if (lane == 0 && nw) base = atomicAdd(&cnt, nw);
        base = __shfl_sync(~0u, base, 0);
        if (pred) {
            int pos = base + __popc(m & ((1u << lane) - 1u));
            if (pos < CAND_CAP) { sv[pos] = x; si[pos] = idx; }
        }
    }
    __syncthreads();
    const int nsurv = (cnt < CAND_CAP) ? cnt : CAND_CAP;

    // parallel rank-based top-NCAND (value desc, index asc)
    for (int p = tid; p < nsurv; p += 256) {
        float v = sv[p]; int i = si[p];
        int rank = 0;
        for (int q = 0; q < nsurv; q++) {
            float vq = sv[q]; int iq = si[q];
            rank += (vq > v) || (vq == v && iq < i);
        }
        if (rank < NCAND) { cvC[rank] = v; ciC[rank] = i; }
    }
    __syncthreads();

    // stage candidate rows into smem, coalesced: warp w -> candidates 4w..4w+3
#pragma unroll
    for (int r = 0; r < 4; r++) {
        int c = (wid << 2) + r;
        const float4* src = reinterpret_cast<const float4*>(
            Mi + (size_t)ciC[c] * ND);
        float* dst = rowsm + c * RSTRIDE;
#pragma unroll
        for (int it = 0; it < 4; it++) {
            int e = lane + (it << 5);
            *reinterpret_cast<float4*>(dst + (e << 2)) = src[e];
        }
    }
    __syncthreads();

    // EXACT rescore: one thread per candidate, sequential ascending-k fp32
    // FMA chain (bit-identical to the reference-matching round-10 order),
    // reading the smem-staged row (values identical to global).
    if (tid < NCAND) {
        const float4* m4 = reinterpret_cast<const float4*>(rowsm + tid * RSTRIDE);
        const float4* q4 = reinterpret_cast<const float4*>(qs);
        float acc = 0.f;
#pragma unroll 8
        for (int it = 0; it < ND / 4; it++) {
            float4 a = q4[it], b = m4[it];
            acc = fmaf(a.x, b.x, acc);
            acc = fmaf(a.y, b.y, acc);
            acc = fmaf(a.z, b.z, acc);
            acc = fmaf(a.w, b.w, acc);
        }
        ceC[tid] = (cvC[tid] > -1e30f) ? acc : -CUDART_INF_F;
    }
    __syncthreads();

    // warp 0: exact ranking of NCAND -> top-10; Z term replacement
    if (wid == 0) {
        float e  = ceC[lane];
        int   ii = ciC[lane];
        bool valid = (e > -1e30f);
        if (valid) {
            int rank = 0;
#pragma unroll
            for (int j = 0; j < NCAND; j++) {
                float ej = ceC[j]; int ij = ciC[j];
                rank += (ej > e) || (ej == e && ij < ii);
            }
            if (rank < 10) { selv[rank] = e; seli[rank] = ii; }
        }
        float dz = valid ? (pexp(e) - pexp(cvC[lane])) : 0.f;
#pragma unroll
        for (int o = 16; o; o >>= 1) dz += __shfl_xor_sync(~0u, dz, o);
        if (lane == 0) zsh += dz;
    }
    __syncthreads();

    const float Z = zsh;
    float p10[10];
#pragma unroll
    for (int j = 0; j < 10; j++) p10[j] = pexp(selv[j]) / Z;
    float wt[5], wb[5], st = 0.f, sb = 0.f;
#pragma unroll
    for (int j = 0; j < 5; j++) { wt[j] = pexp(p10[j]     - p10[0]); st += wt[j]; }
#pragma unroll
    for (int j = 0; j < 5; j++) { wb[j] = pexp(p10[5 + j] - p10[5]); sb += wb[j]; }
    const float rst = 1.f / st, rsb = 1.f / sb;
    int id[10];
#pragma unroll
    for (int j = 0; j < 10; j++) id[j] = seli[j];

    // gather + blend (float2 per thread; 512 = 256*2)
    {
        const int d = tid;
        float2 top = make_float2(0.f, 0.f), bot = make_float2(0.f, 0.f);
#pragma unroll
        for (int j = 0; j < 5; j++) {
            float2 m = reinterpret_cast<const float2*>(Mi + (size_t)id[j] * ND)[d];
            top.x += wt[j] * m.x; top.y += wt[j] * m.y;
        }
#pragma unroll
        for (int j = 0; j < 5; j++) {
            float2 m = reinterpret_cast<const float2*>(Mi + (size_t)id[5 + j] * ND)[d];
            bot.x += wb[j] * m.x; bot.y += wb[j] * m.y;
        }
        float2 q = reinterpret_cast<const float2*>(qs)[d];
        float2 o0, o1;
        o0.x = 0.5f  * q.x + 0.5f  * top.x * rst;
        o0.y = 0.5f  * q.y + 0.5f  * top.y * rst;
        o1.x = 0.01f * q.x + 0.99f * bot.x * rsb;
        o1.y = 0.01f * q.y + 0.99f * bot.y * rsb;
        reinterpret_cast<float2*>(out + (size_t)row * ND)[d] = o0;
        reinterpret_cast<float2*>(out + (size_t)NQ * ND + (size_t)row * ND)[d] = o1;
    }
}

// ---------------------------------------------------------------------------
extern "C" void kernel_launch(void* const* d_in, const int* in_sizes, int n_in,
                              void* d_out, int out_size) {
    const float* Q  = (const float*)d_in[0];
    const float* Mi = (const float*)d_in[1];
    if (n_in >= 2 && in_sizes[0] == NM * ND && in_sizes[1] == NQ * ND) {
        const float* t = Q; Q = Mi; Mi = t;
    }
    float* out = (float*)d_out;

    static int attr_done = 0;
    if (!attr_done) {
        cudaFuncSetAttribute(gemm_hmma,
                             cudaFuncAttributeMaxDynamicSharedMemorySize,
                             SMEM_GEMM);
        cudaFuncSetAttribute(rowpass_kernel,
                             cudaFuncAttributeMaxDynamicSharedMemorySize,
                             SMEM_ROWS);
        attr_done = 1;
    }

    __nv_bfloat16* gA;  cudaGetSymbolAddress((void**)&gA, g_Ab);
    __nv_bfloat16* gB;  cudaGetSymbolAddress((void**)&gB, g_Bb);
    tobf16_kernel<<<(NQ * ND + 255) / 256, 256>>>(Q,  gA, NQ * ND);
    tobf16_kernel<<<(NM * ND + 255) / 256, 256>>>(Mi, gB, NM * ND);

    dim3 gg(NM / BN, NQ / BM);
    gemm_hmma<<<gg, 256, SMEM_GEMM>>>();
    rowpass_kernel<<<NQ, 256, SMEM_ROWS>>>(Q, Mi, out);
}

// round 13
// speedup vs baseline: 1.8352x; 1.4107x over previous
#include <cuda_runtime.h>
#include <cuda_bf16.h>
#include <math_constants.h>
#include <cstdint>

#define NQ 32768
#define NM 2048
#define ND 512
#define BM 128
#define BN 128
#define BK 32
#define KTILES (ND / BK)
#define BKP 40
#define STAGE_ELEMS (128 * BKP)
#define STAGE_BYTES (STAGE_ELEMS * 2)
#define NSTAGE 3
#define SMEM_GEMM (2 * NSTAGE * STAGE_BYTES)   // 61440

#define CAND_CAP 512
#define NCAND 32
#define KTARGET 48
#define CH_FLOATS 128                     // rescore chunk (floats per row)
#define RSTR 132                          // chunk row stride (132 mod 32 = 4)
#define SMEM_ROWS (NCAND * RSTR * 4)      // 16896 B dynamic

// __device__ globals = sanctioned scratch
__device__ __nv_bfloat16  g_Sb[(size_t)NQ * NM];   // 128 MB bf16 scores
__device__ __nv_bfloat16  g_Ab[(size_t)NQ * ND];
__device__ __nv_bfloat16  g_Bb[(size_t)NM * ND];

__device__ __forceinline__ uint32_t smem_u32(const void* p) {
    uint32_t a;
    asm("{ .reg .u64 t; cvta.to.shared.u64 t, %1; cvt.u32.u64 %0, t; }"
        : "=r"(a) : "l"(p));
    return a;
}
#define CP16(dst, src) \
    asm volatile("cp.async.cg.shared.global [%0], [%1], 16;" \
                 :: "r"(dst), "l"(src) : "memory")
#define CP_COMMIT() asm volatile("cp.async.commit_group;" ::: "memory")
#define CP_WAIT1()  asm volatile("cp.async.wait_group 1;" ::: "memory")

#define LDMX4(r0, r1, r2, r3, addr) \
    asm volatile("ldmatrix.sync.aligned.m8n8.x4.shared.b16 {%0,%1,%2,%3}, [%4];" \
                 : "=r"(r0), "=r"(r1), "=r"(r2), "=r"(r3) : "r"(addr))

#define MMA16816(c, a, b0, b1) \
    asm volatile("mma.sync.aligned.m16n8k16.row.col.f32.bf16.bf16.f32 " \
                 "{%0,%1,%2,%3}, {%4,%5,%6,%7}, {%8,%9}, {%0,%1,%2,%3};" \
                 : "+f"((c)[0]), "+f"((c)[1]), "+f"((c)[2]), "+f"((c)[3]) \
                 : "r"((a)[0]), "r"((a)[1]), "r"((a)[2]), "r"((a)[3]),   \
                   "r"(b0), "r"(b1))

// FMA-pipe exp: 2^(x*log2e), degree-6 poly on frac, rel err ~1e-7, |x|<80.
__device__ __forceinline__ float pexp(float x) {
    float t = x * 1.4426950408889634f;
    float n = rintf(t);
    float f = t - n;
    float p = 1.5403530e-4f;
    p = fmaf(p, f, 1.3333558e-3f);
    p = fmaf(p, f, 9.6181291e-3f);
    p = fmaf(p, f, 5.5504109e-2f);
    p = fmaf(p, f, 2.4022651e-1f);
    p = fmaf(p, f, 6.9314718e-1f);
    p = fmaf(p, f, 1.0f);
    return __int_as_float(((int)n + 127) << 23) * p;
}

// ---------------------------------------------------------------------------
__global__ void tobf16_kernel(const float* __restrict__ X,
                              __nv_bfloat16* __restrict__ Y, int total) {
    int i = blockIdx.x * 256 + threadIdx.x;
    if (i < total) Y[i] = __float2bfloat16(X[i]);
}

// ---------------------------------------------------------------------------
// HMMA GEMM (known-good): scores = Ab @ Bb^T, stored as bf16
// ---------------------------------------------------------------------------
__device__ __forceinline__ void load_stage(uint32_t aBase, uint32_t bBase,
                                           int buf, int kt, int row0, int col0,
                                           int tid) {
#pragma unroll
    for (int i = 0; i < 2; i++) {
        int id = tid + (i << 8);
        int r  = id >> 2;
        int kc = (id & 3) << 3;
        uint32_t da = aBase + buf * STAGE_BYTES + (uint32_t)(r * BKP + kc) * 2;
        const __nv_bfloat16* ga = g_Ab + (size_t)(row0 + r) * ND + kt * BK + kc;
        CP16(da, ga);
        uint32_t db = bBase + buf * STAGE_BYTES + (uint32_t)(r * BKP + kc) * 2;
        const __nv_bfloat16* gb = g_Bb + (size_t)(col0 + r) * ND + kt * BK + kc;
        CP16(db, gb);
    }
}

__global__ __launch_bounds__(256)
void gemm_hmma() {
    extern __shared__ __nv_bfloat16 sm[];
    const int tid = threadIdx.x, lane = tid & 31, wid = tid >> 5;
    const int row0 = blockIdx.y * BM, col0 = blockIdx.x * BN;
    const int mw = (wid >> 1) * 32;
    const int nw = (wid & 1) * 64;
    uint32_t aBase = smem_u32(sm);
    uint32_t bBase = aBase + NSTAGE * STAGE_BYTES;

    const int a_row = lane & 15;
    const int a_k8  = (lane >> 4) << 3;
    const int b_row = (lane & 7) + ((lane >> 4) << 3);
    const int b_k8  = ((lane >> 3) & 1) << 3;

    float c[2][8][4];
#pragma unroll
    for (int mt = 0; mt < 2; mt++)
#pragma unroll
        for (int nt = 0; nt < 8; nt++)
#pragma unroll
            for (int r = 0; r < 4; r++) c[mt][nt][r] = 0.f;

    load_stage(aBase, bBase, 0, 0, row0, col0, tid); CP_COMMIT();
    load_stage(aBase, bBase, 1, 1, row0, col0, tid); CP_COMMIT();

    for (int s = 0; s < KTILES; s++) {
        if (s + 2 < KTILES)
            load_stage(aBase, bBase, (s + 2) % NSTAGE, s + 2, row0, col0, tid);
        CP_COMMIT();
        CP_WAIT1();
        __syncthreads();

        const int buf = s % NSTAGE;
#pragma unroll
        for (int k16 = 0; k16 < BK; k16 += 16) {
            uint32_t a[2][4], b[4][4];
#pragma unroll
            for (int mt = 0; mt < 2; mt++) {
                uint32_t addr = aBase + buf * STAGE_BYTES +
                    (uint32_t)((mw + mt * 16 + a_row) * BKP + k16 + a_k8) * 2;
                LDMX4(a[mt][0], a[mt][1], a[mt][2], a[mt][3], addr);
            }
#pragma unroll
            for (int np = 0; np < 4; np++) {
                uint32_t addr = bBase + buf * STAGE_BYTES +
                    (uint32_t)((nw + np * 16 + b_row) * BKP + k16 + b_k8) * 2;
                LDMX4(b[np][0], b[np][1], b[np][2], b[np][3], addr);
            }
#pragma unroll
            for (int mt = 0; mt < 2; mt++)
#pragma unroll
                for (int nt = 0; nt < 8; nt++)
                    MMA16816(c[mt][nt], a[mt],
                             b[nt >> 1][(nt & 1) * 2],
                             b[nt >> 1][(nt & 1) * 2 + 1]);
        }
        __syncthreads();
    }

#pragma unroll
    for (int mt = 0; mt < 2; mt++) {
        int r0r = row0 + mw + mt * 16 + (lane >> 2);
#pragma unroll
        for (int nt = 0; nt < 8; nt++) {
            int col = col0 + nw + nt * 8 + (lane & 3) * 2;
            __nv_bfloat162 b0 = __floats2bfloat162_rn(c[mt][nt][0], c[mt][nt][1]);
            __nv_bfloat162 b1 = __floats2bfloat162_rn(c[mt][nt][2], c[mt][nt][3]);
            *reinterpret_cast<__nv_bfloat162*>(&g_Sb[(size_t)r0r * NM + col])       = b0;
            *reinterpret_cast<__nv_bfloat162*>(&g_Sb[(size_t)(r0r + 8) * NM + col]) = b1;
        }
    }
}

// ---------------------------------------------------------------------------
// Rowpass v12: bf16 scores (one uint4 load/thread); registers-only pass 1;
// warp-aggregated hist/compaction; rank-based top-32; CHUNKED candidate
// staging (4 x 128 floats, 16.9KB smem) with the exact sequential
// ascending-k fp32 rescore chain carried across chunks (bit-identical order).
// ---------------------------------------------------------------------------
__global__ __launch_bounds__(256)
void rowpass_kernel(const float* __restrict__ Q, const float* __restrict__ Mi,
                    float* __restrict__ out) {
    extern __shared__ float rowsm[];      // NCAND x RSTR floats (16.9 KB)
    __shared__ float  qs[ND];
    __shared__ float  sv[CAND_CAP];
    __shared__ int    si[CAND_CAP];
    __shared__ int    hist[32];
    __shared__ float  warpmax[8], warpsum[8];
    __shared__ float  cvC[NCAND];
    __shared__ int    ciC[NCAND];
    __shared__ float  ceC[NCAND];
    __shared__ float  selv[10];
    __shared__ int    seli[10];
    __shared__ float  zsh, mxsh, thrsh;
    __shared__ int    cnt, widef;

    const int tid = threadIdx.x, lane = tid & 31, wid = tid >> 5;
    const int row = blockIdx.x;

    // one uint4 = 8 bf16 scores per thread
    uint4 sraw = reinterpret_cast<const uint4*>(g_Sb + (size_t)row * NM)[tid];
    float e0[8];
    {
        const __nv_bfloat162* pp = reinterpret_cast<const __nv_bfloat162*>(&sraw);
#pragma unroll
        for (int h = 0; h < 4; h++) {
            float2 f = __bfloat1622float2(pp[h]);
            e0[2 * h] = f.x; e0[2 * h + 1] = f.y;
        }
    }

    if (tid < 10) { selv[tid] = 0.f; seli[tid] = 0; }
    if (tid < 32) { hist[tid] = 0; cvC[tid] = -CUDART_INF_F; ciC[tid] = 0; }
    if (tid == 0) cnt = 0;
    {
        const float2* q2 = reinterpret_cast<const float2*>(Q + (size_t)row * ND);
        reinterpret_cast<float2*>(qs)[tid] = q2[tid];
    }

    // rowmax + Z (poly-exp) from registers
    float lmax = -CUDART_INF_F, lsum = 0.f;
#pragma unroll
    for (int j = 0; j < 8; j++) {
        lmax = fmaxf(lmax, e0[j]);
        lsum += pexp(e0[j]);
    }
#pragma unroll
    for (int o = 16; o; o >>= 1) {
        lmax = fmaxf(lmax, __shfl_xor_sync(~0u, lmax, o));
        lsum += __shfl_xor_sync(~0u, lsum, o);
    }
    if (lane == 0) { warpmax[wid] = lmax; warpsum[wid] = lsum; }
    __syncthreads();
    if (tid == 0) {
        float m = warpmax[0], z = warpsum[0];
        for (int w = 1; w < 8; w++) { m = fmaxf(m, warpmax[w]); z += warpsum[w]; }
        mxsh = m; zsh = z;
    }
    __syncthreads();
    const float mx = mxsh;

    // histogram (32 bins, width 1/16 over (mx-2, mx]) — warp-aggregated
#pragma unroll
    for (int j = 0; j < 8; j++) {
        float d = (mx - e0[j]) * 16.f;
        bool inr = d < 32.f;
        int bin = inr ? (int)d : 0;
        unsigned act = __ballot_sync(~0u, inr);
        if (inr) {
            unsigned m = __match_any_sync(act, bin);
            int leader = __ffs(m) - 1;
            if (lane == leader) atomicAdd(&hist[bin], __popc(m));
        }
    }
    __syncthreads();
    if (wid == 0) {
        int c = hist[lane];
#pragma unroll
        for (int o = 1; o < 32; o <<= 1) {
            int t = __shfl_up_sync(~0u, c, o);
            if (lane >= o) c += t;
        }
        unsigned m = __ballot_sync(~0u, c >= KTARGET);
        if (lane == 0) {
            if (m) {
                int b = __ffs(m) - 1;
                thrsh = mx - (float)(b + 1) * (1.f / 16.f);
                widef = 0;
            } else widef = 1;
        }
    }
    __syncthreads();

    if (widef) {   // rare: outlier max, widen to (mx-4, mx]
        if (tid < 32) hist[tid] = 0;
        __syncthreads();
#pragma unroll
        for (int j = 0; j < 8; j++) {
            float d = (mx - e0[j]) * 8.f;
            bool inr = d < 32.f;
            int bin = inr ? (int)d : 0;
            unsigned act = __ballot_sync(~0u, inr);
            if (inr) {
                unsigned m = __match_any_sync(act, bin);
                int leader = __ffs(m) - 1;
                if (lane == leader) atomicAdd(&hist[bin], __popc(m));
            }
        }
        __syncthreads();
        if (wid == 0) {
            int c = hist[lane];
#pragma unroll
            for (int o = 1; o < 32; o <<= 1) {
                int t = __shfl_up_sync(~0u, c, o);
                if (lane >= o) c += t;
            }
            unsigned m = __ballot_sync(~0u, c >= KTARGET);
            if (lane == 0) {
                if (m) {
                    int b = __ffs(m) - 1;
                    thrsh = mx - (float)(b + 1) * 0.125f;
                } else thrsh = mx - 4.f;
            }
        }
        __syncthreads();
    }
    const float thr = thrsh;

    // compaction from registers — warp-aggregated offsets
#pragma unroll
    for (int j = 0; j < 8; j++) {
        float x = e0[j];
        int idx = tid * 8 + j;
        bool pred = x > thr;
        unsigned m = __ballot_sync(~0u, pred);
        int nw = __popc(m);
        int base = 0;
        if (lane == 0 && nw) base = atomicAdd(&cnt, nw);
        base = __shfl_sync(~0u, base, 0);
        if (pred) {
            int pos = base + __popc(m & ((1u << lane) - 1u));
            if (pos < CAND_CAP) { sv[pos] = x; si[pos] = idx; }
        }
    }
    __syncthreads();
    const int nsurv = (cnt < CAND_CAP) ? cnt : CAND_CAP;

    // parallel rank-based top-NCAND (value desc, index asc)
    for (int p = tid; p < nsurv; p += 256) {
        float v = sv[p]; int i = si[p];
        int rank = 0;
        for (int q = 0; q < nsurv; q++) {
            float vq = sv[q]; int iq = si[q];
            rank += (vq > v) || (vq == v && iq < i);
        }
        if (rank < NCAND) { cvC[rank] = v; ciC[rank] = i; }
    }

    // chunked staging + EXACT sequential ascending-k fp32 chain.
    // acc carried across chunks: identical adds, identical order.
    float acc = 0.f;
    for (int ch = 0; ch < ND / CH_FLOATS; ch++) {
        __syncthreads();   // rank results visible (ch=0) / prev chains done
        {
            int c0 = wid << 2;
#pragma unroll
            for (int r = 0; r < 4; r++) {
                const float4* src = reinterpret_cast<const float4*>(
                    Mi + (size_t)ciC[c0 + r] * ND) + (ch << 5);
                *reinterpret_cast<float4*>(
                    rowsm + (c0 + r) * RSTR + (lane << 2)) = src[lane];
            }
        }
        __syncthreads();
        if (tid < NCAND) {
            const float4* m4 = reinterpret_cast<const float4*>(rowsm + tid * RSTR);
            const float4* q4 = reinterpret_cast<const float4*>(qs) + (ch << 5);
#pragma unroll 8
            for (int it = 0; it < CH_FLOATS / 4; it++) {
                float4 a = q4[it], b = m4[it];
                acc = fmaf(a.x, b.x, acc);
                acc = fmaf(a.y, b.y, acc);
                acc = fmaf(a.z, b.z, acc);
                acc = fmaf(a.w, b.w, acc);
            }
        }
    }
    if (tid < NCAND)
        ceC[tid] = (cvC[tid] > -1e30f) ? acc : -CUDART_INF_F;
    __syncthreads();

    // warp 0: exact ranking of NCAND -> top-10; Z term replacement
    if (wid == 0) {
        float e  = ceC[lane];
        int   ii = ciC[lane];
        bool valid = (e > -1e30f);
        if (valid) {
            int rank = 0;
#pragma unroll
            for (int j = 0; j < NCAND; j++) {
                float ej = ceC[j]; int ij = ciC[j];
                rank += (ej > e) || (ej == e && ij < ii);
            }
            if (rank < 10) { selv[rank] = e; seli[rank] = ii; }
        }
        float dz = valid ? (pexp(e) - pexp(cvC[lane])) : 0.f;
#pragma unroll
        for (int o = 16; o; o >>= 1) dz += __shfl_xor_sync(~0u, dz, o);
        if (lane == 0) zsh += dz;
    }
    __syncthreads();

    const float Z = zsh;
    float p10[10];
#pragma unroll
    for (int j = 0; j < 10; j++) p10[j] = pexp(selv[j]) / Z;
    float wt[5], wb[5], st = 0.f, sb = 0.f;
#pragma unroll
    for (int j = 0; j < 5; j++) { wt[j] = pexp(p10[j]     - p10[0]); st += wt[j]; }
#pragma unroll
    for (int j = 0; j < 5; j++) { wb[j] = pexp(p10[5 + j] - p10[5]); sb += wb[j]; }
    const float rst = 1.f / st, rsb = 1.f / sb;
    int id[10];
#pragma unroll
    for (int j = 0; j < 10; j++) id[j] = seli[j];

    // gather + blend (float2 per thread; 512 = 256*2)
    {
        const int d = tid;
        float2 top = make_float2(0.f, 0.f), bot = make_float2(0.f, 0.f);
#pragma unroll
        for (int j = 0; j < 5; j++) {
            float2 m = reinterpret_cast<const float2*>(Mi + (size_t)id[j] * ND)[d];
            top.x += wt[j] * m.x; top.y += wt[j] * m.y;
        }
#pragma unroll
        for (int j = 0; j < 5; j++) {
            float2 m = reinterpret_cast<const float2*>(Mi + (size_t)id[5 + j] * ND)[d];
            bot.x += wb[j] * m.x; bot.y += wb[j] * m.y;
        }
        float2 q = reinterpret_cast<const float2*>(qs)[d];
        float2 o0, o1;
        o0.x = 0.5f  * q.x + 0.5f  * top.x * rst;
        o0.y = 0.5f  * q.y + 0.5f  * top.y * rst;
        o1.x = 0.01f * q.x + 0.99f * bot.x * rsb;
        o1.y = 0.01f * q.y + 0.99f * bot.y * rsb;
        reinterpret_cast<float2*>(out + (size_t)row * ND)[d] = o0;
        reinterpret_cast<float2*>(out + (size_t)NQ * ND + (size_t)row * ND)[d] = o1;
    }
}

// ---------------------------------------------------------------------------
extern "C" void kernel_launch(void* const* d_in, const int* in_sizes, int n_in,
                              void* d_out, int out_size) {
    const float* Q  = (const float*)d_in[0];
    const float* Mi = (const float*)d_in[1];
    if (n_in >= 2 && in_sizes[0] == NM * ND && in_sizes[1] == NQ * ND) {
        const float* t = Q; Q = Mi; Mi = t;
    }
    float* out = (float*)d_out;

    static int attr_done = 0;
    if (!attr_done) {
        cudaFuncSetAttribute(gemm_hmma,
                             cudaFuncAttributeMaxDynamicSharedMemorySize,
                             SMEM_GEMM);
        cudaFuncSetAttribute(rowpass_kernel,
                             cudaFuncAttributeMaxDynamicSharedMemorySize,
                             SMEM_ROWS);
        attr_done = 1;
    }

    __nv_bfloat16* gA;  cudaGetSymbolAddress((void**)&gA, g_Ab);
    __nv_bfloat16* gB;  cudaGetSymbolAddress((void**)&gB, g_Bb);
    tobf16_kernel<<<(NQ * ND + 255) / 256, 256>>>(Q,  gA, NQ * ND);
    tobf16_kernel<<<(NM * ND + 255) / 256, 256>>>(Mi, gB, NM * ND);

    dim3 gg(NM / BN, NQ / BM);
    gemm_hmma<<<gg, 256, SMEM_GEMM>>>();
    rowpass_kernel<<<NQ, 256, SMEM_ROWS>>>(Q, Mi, out);
}